// round 1
// baseline (speedup 1.0000x reference)
#include <cuda_runtime.h>
#include <cstdint>

// Problem constants
#define T_TOK   262144
#define D_IN    128
#define D_H     256
#define D_OUT   128
#define N_SEG   8192
#define TILE_M  128
#define CHUNK   64
#define NCHUNK  (D_H / CHUNK)   // 4

// Scratch for h2 (device global — allocation-free per harness rules). 134 MB.
__device__ float g_h2[(size_t)T_TOK * D_OUT];

// Shared-memory strides (floats), chosen for conflict-free MMA fragment loads:
//  A-pattern bank = (stride%32)*gr + gc must be a bijection over 32 lanes
//  B-pattern bank = (stride%32)*gc + gr must be a bijection over 32 lanes
#define XS_STRIDE 132   // 132%32=4  : A-pattern 4*gr+gc unique
#define W1_STRIDE 72    // 72%32=8   : B-pattern 8*gc+gr unique
#define H1_STRIDE 76    // 76%32=12  : A-pattern 12*gr+gc unique
#define W2_STRIDE 136   // 136%32=8  : B-pattern 8*gc+gr unique

// float counts: xs 128*132 + w1s 128*72 + h1s 128*76 + w2s 64*136 + b1 256 + b2 128
#define SMEM_FLOATS (128*XS_STRIDE + 128*W1_STRIDE + 128*H1_STRIDE + 64*W2_STRIDE + 256 + 128)
#define SMEM_BYTES  (SMEM_FLOATS * 4)   // 179,712 B

__device__ __forceinline__ uint32_t f2tf32(float x) {
    uint32_t r;
    asm("cvt.rna.tf32.f32 %0, %1;" : "=r"(r) : "f"(x));
    return r;
}

__device__ __forceinline__ void mma_tf32(float* c, const uint32_t* a, const uint32_t* b) {
    asm volatile(
        "mma.sync.aligned.m16n8k8.row.col.f32.tf32.tf32.f32 "
        "{%0,%1,%2,%3}, {%4,%5,%6,%7}, {%8,%9}, {%0,%1,%2,%3};"
        : "+f"(c[0]), "+f"(c[1]), "+f"(c[2]), "+f"(c[3])
        : "r"(a[0]), "r"(a[1]), "r"(a[2]), "r"(a[3]), "r"(b[0]), "r"(b[1]));
}

// ============================================================================
// Kernel 1: fused MLP. One CTA = 128 tokens. 8 warps, each owns 16 token rows.
// Layer chaining: loop D_H in chunks of 64; h1 chunk bounced through smem,
// h2 accumulators live in registers across chunks.
// ============================================================================
__global__ void __launch_bounds__(256, 1) mlp_kernel(
    const float* __restrict__ x,
    const float* __restrict__ W1, const float* __restrict__ b1,
    const float* __restrict__ W2, const float* __restrict__ b2)
{
    extern __shared__ uint32_t smem[];
    uint32_t* xs  = smem;                       // [128][XS_STRIDE] tf32
    uint32_t* w1s = xs  + 128 * XS_STRIDE;      // [128][W1_STRIDE] tf32
    uint32_t* h1s = w1s + 128 * W1_STRIDE;      // [128][H1_STRIDE] tf32
    uint32_t* w2s = h1s + 128 * H1_STRIDE;      // [64][W2_STRIDE]  tf32
    float* b1s = (float*)(w2s + 64 * W2_STRIDE);
    float* b2s = b1s + 256;

    const int tid  = threadIdx.x;
    const int warp = tid >> 5;
    const int lane = tid & 31;
    const int gr = lane >> 2;   // fragment group row 0..7
    const int gc = lane & 3;    // fragment group col 0..3
    const int r0 = warp * 16;
    const long tile0 = (long)blockIdx.x * TILE_M;

    // ---- Stage x tile (coalesced float4) with round-to-nearest tf32 conversion
    {
        const float4* xg = (const float4*)(x + tile0 * D_IN);
        #pragma unroll 4
        for (int i = tid; i < TILE_M * D_IN / 4; i += 256) {
            float4 v = xg[i];
            int r = (i * 4) / D_IN, c = (i * 4) % D_IN;
            uint32_t* d = &xs[r * XS_STRIDE + c];
            d[0] = f2tf32(v.x); d[1] = f2tf32(v.y);
            d[2] = f2tf32(v.z); d[3] = f2tf32(v.w);
        }
        if (tid < D_H)  b1s[tid] = b1[tid];
        if (tid < D_OUT) b2s[tid] = b2[tid];
    }

    float h2acc[16][4];
    #pragma unroll
    for (int nt = 0; nt < 16; ++nt)
        #pragma unroll
        for (int j = 0; j < 4; ++j) h2acc[nt][j] = 0.f;

    for (int ch = 0; ch < NCHUNK; ++ch) {
        __syncthreads();   // prior chunk's layer2 reads of h1s/w2s complete

        // ---- Stage W1 chunk [128 x 64] and W2 chunk [64 x 128]
        #pragma unroll 2
        for (int i = tid; i < 128 * 64 / 4; i += 256) {
            int k = (i * 4) / 64, n = (i * 4) % 64;
            float4 v = *(const float4*)(W1 + k * D_H + ch * 64 + n);
            uint32_t* d = &w1s[k * W1_STRIDE + n];
            d[0] = f2tf32(v.x); d[1] = f2tf32(v.y);
            d[2] = f2tf32(v.z); d[3] = f2tf32(v.w);
        }
        #pragma unroll 2
        for (int i = tid; i < 64 * 128 / 4; i += 256) {
            int k = (i * 4) / 128, n = (i * 4) % 128;
            float4 v = *(const float4*)(W2 + (ch * 64 + k) * D_OUT + n);
            uint32_t* d = &w2s[k * W2_STRIDE + n];
            d[0] = f2tf32(v.x); d[1] = f2tf32(v.y);
            d[2] = f2tf32(v.z); d[3] = f2tf32(v.w);
        }
        __syncthreads();

        // ---- Layer 1: h1c[16 x 64] per warp  (M=16, N=64, K=128)
        float acc1[8][4];
        #pragma unroll
        for (int nt = 0; nt < 8; ++nt)
            #pragma unroll
            for (int j = 0; j < 4; ++j) acc1[nt][j] = 0.f;

        #pragma unroll
        for (int kt = 0; kt < 16; ++kt) {
            const int k0 = kt * 8;
            uint32_t a[4];
            a[0] = xs[(r0 + gr)     * XS_STRIDE + k0 + gc];
            a[1] = xs[(r0 + 8 + gr) * XS_STRIDE + k0 + gc];
            a[2] = xs[(r0 + gr)     * XS_STRIDE + k0 + 4 + gc];
            a[3] = xs[(r0 + 8 + gr) * XS_STRIDE + k0 + 4 + gc];
            #pragma unroll
            for (int nt = 0; nt < 8; ++nt) {
                uint32_t b[2];
                b[0] = w1s[(k0 + gc)     * W1_STRIDE + nt * 8 + gr];
                b[1] = w1s[(k0 + 4 + gc) * W1_STRIDE + nt * 8 + gr];
                mma_tf32(acc1[nt], a, b);
            }
        }

        // ---- bias + ReLU -> h1s (tf32)
        #pragma unroll
        for (int nt = 0; nt < 8; ++nt) {
            const int n = nt * 8 + gc * 2;
            const float bb0 = b1s[ch * 64 + n];
            const float bb1 = b1s[ch * 64 + n + 1];
            h1s[(r0 + gr)     * H1_STRIDE + n]     = f2tf32(fmaxf(acc1[nt][0] + bb0, 0.f));
            h1s[(r0 + gr)     * H1_STRIDE + n + 1] = f2tf32(fmaxf(acc1[nt][1] + bb1, 0.f));
            h1s[(r0 + 8 + gr) * H1_STRIDE + n]     = f2tf32(fmaxf(acc1[nt][2] + bb0, 0.f));
            h1s[(r0 + 8 + gr) * H1_STRIDE + n + 1] = f2tf32(fmaxf(acc1[nt][3] + bb1, 0.f));
        }
        __syncthreads();

        // ---- Layer 2 partial: h2 += h1c[16 x 64] @ W2c[64 x 128]
        #pragma unroll
        for (int kt = 0; kt < 8; ++kt) {
            const int k0 = kt * 8;
            uint32_t a[4];
            a[0] = h1s[(r0 + gr)     * H1_STRIDE + k0 + gc];
            a[1] = h1s[(r0 + 8 + gr) * H1_STRIDE + k0 + gc];
            a[2] = h1s[(r0 + gr)     * H1_STRIDE + k0 + 4 + gc];
            a[3] = h1s[(r0 + 8 + gr) * H1_STRIDE + k0 + 4 + gc];
            #pragma unroll
            for (int nt = 0; nt < 16; ++nt) {
                uint32_t b[2];
                b[0] = w2s[(k0 + gc)     * W2_STRIDE + nt * 8 + gr];
                b[1] = w2s[(k0 + 4 + gc) * W2_STRIDE + nt * 8 + gr];
                mma_tf32(h2acc[nt], a, b);
            }
        }
    }

    __syncthreads();   // all warps done reading xs (last read: layer1 of chunk 3)

    // ---- bias2 + ReLU -> stage h2 in smem (reuse xs region) as float
    float* h2s = (float*)xs;
    #pragma unroll
    for (int nt = 0; nt < 16; ++nt) {
        const int n = nt * 8 + gc * 2;
        const float bb0 = b2s[n], bb1 = b2s[n + 1];
        h2s[(r0 + gr)     * XS_STRIDE + n]     = fmaxf(h2acc[nt][0] + bb0, 0.f);
        h2s[(r0 + gr)     * XS_STRIDE + n + 1] = fmaxf(h2acc[nt][1] + bb1, 0.f);
        h2s[(r0 + 8 + gr) * XS_STRIDE + n]     = fmaxf(h2acc[nt][2] + bb0, 0.f);
        h2s[(r0 + 8 + gr) * XS_STRIDE + n + 1] = fmaxf(h2acc[nt][3] + bb1, 0.f);
    }
    __syncthreads();

    // ---- Coalesced float4 write to global scratch
    float4* og = (float4*)(g_h2 + tile0 * D_OUT);
    #pragma unroll 4
    for (int i = tid; i < TILE_M * D_OUT / 4; i += 256) {
        int r = (i * 4) / D_OUT, c = (i * 4) % D_OUT;
        const float* s = &h2s[r * XS_STRIDE + c];
        og[i] = make_float4(s[0], s[1], s[2], s[3]);
    }
}

// ============================================================================
// Kernel 2: per-segment mean. segment_ids are sorted -> binary search bounds.
// Deterministic (fixed summation order, no atomics).
// ============================================================================
__global__ void __launch_bounds__(128) pool_kernel(
    const int* __restrict__ seg, float* __restrict__ out)
{
    const int s = blockIdx.x;
    __shared__ int bounds[2];
    if (threadIdx.x == 0) {
        int lo = 0, hi = T_TOK;
        while (lo < hi) { int m = (lo + hi) >> 1; if (seg[m] < s) lo = m + 1; else hi = m; }
        bounds[0] = lo;
        hi = T_TOK;
        while (lo < hi) { int m = (lo + hi) >> 1; if (seg[m] < s + 1) lo = m + 1; else hi = m; }
        bounds[1] = lo;
    }
    __syncthreads();
    const int st = bounds[0], en = bounds[1];
    float acc = 0.f;
    for (int r = st; r < en; ++r)
        acc += g_h2[(long)r * D_OUT + threadIdx.x];
    const float cnt = (float)(en - st);
    out[s * D_OUT + threadIdx.x] = acc / fmaxf(cnt, 1.f);
}

// ============================================================================
// kernel_launch: map inputs by element count (robust to num_segments being a
// scalar input or absent), then run mlp -> pool. Graph-capturable: kernel
// launches only; cudaFuncSetAttribute is not a stream op.
// ============================================================================
extern "C" void kernel_launch(void* const* d_in, const int* in_sizes, int n_in,
                              void* d_out, int out_size)
{
    const float* x  = nullptr;
    const int*   sg = nullptr;
    const float* W1 = nullptr; const float* B1 = nullptr;
    const float* W2 = nullptr; const float* B2 = nullptr;

    int w_seen = 0;
    for (int i = 0; i < n_in; ++i) {
        const int sz = in_sizes[i];
        if (sz == T_TOK * D_IN)      x  = (const float*)d_in[i];
        else if (sz == T_TOK)        sg = (const int*)d_in[i];
        else if (sz == D_IN * D_H) { if (w_seen++ == 0) W1 = (const float*)d_in[i];
                                     else               W2 = (const float*)d_in[i]; }
        else if (sz == D_H)          B1 = (const float*)d_in[i];
        else if (sz == D_OUT)        B2 = (const float*)d_in[i];
        // size-1 scalar (num_segments) ignored: N_SEG is compile-time
    }

    cudaFuncSetAttribute(mlp_kernel, cudaFuncAttributeMaxDynamicSharedMemorySize, SMEM_BYTES);

    mlp_kernel<<<T_TOK / TILE_M, 256, SMEM_BYTES>>>(x, W1, B1, W2, B2);
    pool_kernel<<<N_SEG, 128>>>(sg, (float*)d_out);
}

// round 3
// speedup vs baseline: 2.6687x; 2.6687x over previous
#include <cuda_runtime.h>
#include <cuda_fp16.h>
#include <cstdint>

#define T_TOK   262144
#define D_IN    128
#define D_H     256
#define D_OUT   128
#define N_SEG   8192
#define TILE_M  128
#define NTILES  (T_TOK / TILE_M)
#define NCHUNK  4            // D_H chunks of 64

// ---------------- device scratch ----------------
__device__ __half   g_h2h[(size_t)T_TOK * D_OUT];   // 67 MB fp16 h2 scratch
__device__ uint32_t g_w1img[4][4096];               // 4 chunks x 16KB swizzled fp16 [k=128][n=64]
__device__ uint32_t g_w2img[4][4096];               // 4 chunks x 16KB: 2 panels [k=64][n=64]
__device__ int      g_segstart[N_SEG + 1];

// ---------------- SMEM layout (bytes) ----------------
#define SM_B1    0          // fp32[256]
#define SM_B2    1024       // fp32[128]
#define SM_XS0   2048       // x panel k0..63   [128 x 128B] SW128
#define SM_XS1   18432      // x panel k64..127
#define SM_W1A   34816      // w1 buf A [128 x 128B]
#define SM_W1B   51200      // w1 buf B
#define SM_W2    67584      // w2 chunk: 2 panels [64 x 128B] (16KB)
#define SM_H1    83968      // h1 chunk [128 x 128B]
#define SMEM_BYTES 100352   // 98KB -> 2 CTAs/SM
#define SM_OS    2048       // epilogue2 staging (reuses XS0/XS1/W1A head)
#define OS_STRIDE 136       // halves; row stride 272B (16B aligned)

__device__ __forceinline__ uint32_t sw(uint32_t b) { return b ^ ((b >> 3) & 0x70); }

__device__ __forceinline__ uint32_t smem_u32(const void* p) {
    uint32_t a;
    asm("{ .reg .u64 t; cvta.to.shared.u64 t, %1; cvt.u32.u64 %0, t; }" : "=r"(a) : "l"(p));
    return a;
}
__device__ __forceinline__ void ldmA(uint32_t* a, uint32_t addr) {
    asm volatile("ldmatrix.sync.aligned.m8n8.x4.shared.b16 {%0,%1,%2,%3}, [%4];"
        : "=r"(a[0]), "=r"(a[1]), "=r"(a[2]), "=r"(a[3]) : "r"(addr));
}
__device__ __forceinline__ void ldmBT(uint32_t* b, uint32_t addr) {
    asm volatile("ldmatrix.sync.aligned.m8n8.x4.trans.shared.b16 {%0,%1,%2,%3}, [%4];"
        : "=r"(b[0]), "=r"(b[1]), "=r"(b[2]), "=r"(b[3]) : "r"(addr));
}
__device__ __forceinline__ void mma_f16(float* c, const uint32_t* a, const uint32_t* b) {
    asm volatile(
        "mma.sync.aligned.m16n8k16.row.col.f32.f16.f16.f32 "
        "{%0,%1,%2,%3}, {%4,%5,%6,%7}, {%8,%9}, {%0,%1,%2,%3};"
        : "+f"(c[0]), "+f"(c[1]), "+f"(c[2]), "+f"(c[3])
        : "r"(a[0]), "r"(a[1]), "r"(a[2]), "r"(a[3]), "r"(b[0]), "r"(b[1]));
}
__device__ __forceinline__ void cpa16(uint32_t saddr, const void* g) {
    asm volatile("cp.async.cg.shared.global [%0], [%1], 16;" :: "r"(saddr), "l"(g));
}
#define CP_COMMIT() asm volatile("cp.async.commit_group;" ::: "memory")
#define CP_WAIT0()  asm volatile("cp.async.wait_group 0;" ::: "memory")
#define CP_WAIT1()  asm volatile("cp.async.wait_group 1;" ::: "memory")

// ============================================================================
// Prep 1: fp16, transposed-for-B, SW128-swizzled weight images (linear copyable)
// w1 image ch: panel [k=0..127][n_local=0..63], source W1[k][ch*64+n]
// w2 image ch: panels p=0,1: [k_local=0..63][n_local=0..63], src W2[ch*64+k][p*64+n]
// ============================================================================
__global__ void prep_weights(const float* __restrict__ W1, const float* __restrict__ W2)
{
    int idx = blockIdx.x * blockDim.x + threadIdx.x;     // 0..32767 words
    if (idx < 16384) {                                   // w1
        int ch = idx >> 12, w = idx & 4095;
        uint32_t s = sw(w * 4);                          // involution
        int k = s >> 7, nl = (s & 127) >> 1;
        __half2 v = __floats2half2_rn(W1[k * D_H + ch * 64 + nl],
                                      W1[k * D_H + ch * 64 + nl + 1]);
        g_w1img[ch][w] = *(uint32_t*)&v;
    } else {                                             // w2
        int i2 = idx - 16384;
        int ch = i2 >> 12, w = i2 & 4095;
        int p = w >> 11, wi = w & 2047;
        uint32_t s = sw(wi * 4);
        int kl = s >> 7, nl = (s & 127) >> 1;
        int k = ch * 64 + kl, n = p * 64 + nl;
        __half2 v = __floats2half2_rn(W2[k * D_OUT + n], W2[k * D_OUT + n + 1]);
        g_w2img[ch][w] = *(uint32_t*)&v;
    }
}

// Prep 2: segment start offsets (ids sorted)
__global__ void prep_bounds(const int* __restrict__ seg)
{
    int i = blockIdx.x * blockDim.x + threadIdx.x;
    if (i >= T_TOK) return;
    int s  = seg[i];
    int sp = (i == 0) ? -1 : seg[i - 1];
    for (int t = sp + 1; t <= s; ++t) g_segstart[t] = i;
    if (i == T_TOK - 1)
        for (int t = s + 1; t <= N_SEG; ++t) g_segstart[t] = T_TOK;
}

// ============================================================================
// Fused MLP, fp16 mma + ldmatrix. CTA = 128 tokens, 8 warps x 16 rows, occ 2.
// ============================================================================
__global__ void __launch_bounds__(256, 2) mlp_kernel(
    const float* __restrict__ x,
    const float* __restrict__ b1, const float* __restrict__ b2)
{
    extern __shared__ char smem[];
    const uint32_t sbase = smem_u32(smem);
    const int tid = threadIdx.x, wid = tid >> 5, lane = tid & 31;
    const int l15 = lane & 15;
    const int colh = (lane >> 4) & 1;          // +16B column-half for ldmatrix
    const int gr = lane >> 2, gc = lane & 3;
    const int r0 = wid * 16;
    const long tile0 = (long)blockIdx.x * TILE_M;

    float* b1s = (float*)(smem + SM_B1);
    float* b2s = (float*)(smem + SM_B2);
    b1s[tid] = b1[tid & 255];
    if (tid < D_OUT) b2s[tid] = b2[tid];

    // ---- stage x -> fp16 SW128 panels ----
    {
        const float4* xg = (const float4*)(x + tile0 * D_IN);
        #pragma unroll 4
        for (int i = tid; i < TILE_M * D_IN / 4; i += 256) {
            float4 v = xg[i];
            int r = i >> 5, k0 = (i & 31) * 4;
            uint32_t pan = (k0 >= 64) ? SM_XS1 : SM_XS0;
            uint32_t a = sbase + pan + sw((uint32_t)(r * 128 + (k0 & 63) * 2));
            __half2 h0 = __floats2half2_rn(v.x, v.y);
            __half2 h1 = __floats2half2_rn(v.z, v.w);
            asm volatile("st.shared.v2.b32 [%0], {%1,%2};"
                :: "r"(a), "r"(*(uint32_t*)&h0), "r"(*(uint32_t*)&h1) : "memory");
        }
    }
    // ---- prefetch w1[0] and w2[0] ----
    {
        const uint4* s1 = (const uint4*)g_w1img[0];
        for (int i = tid; i < 1024; i += 256) cpa16(sbase + SM_W1A + i * 16, s1 + i);
        CP_COMMIT();
        const uint4* s2 = (const uint4*)g_w2img[0];
        for (int i = tid; i < 1024; i += 256) cpa16(sbase + SM_W2 + i * 16, s2 + i);
        CP_COMMIT();
    }

    const uint32_t rA = (uint32_t)((r0 + l15) * 128);   // A-row byte offset

    float h2acc[16][4];
    #pragma unroll
    for (int t = 0; t < 16; ++t)
        #pragma unroll
        for (int j = 0; j < 4; ++j) h2acc[t][j] = 0.f;

    #pragma unroll 1
    for (int ch = 0; ch < NCHUNK; ++ch) {
        CP_WAIT1();            // w1[ch] landed
        __syncthreads();       // x/bias/h1-reads-of-prev-chunk all settled

        const uint32_t w1pan = (ch & 1) ? SM_W1B : SM_W1A;

        // ---- layer 1: acc1[16 x 64] = x[16 x 128] @ W1c[128 x 64] ----
        float acc1[8][4];
        #pragma unroll
        for (int t = 0; t < 8; ++t)
            #pragma unroll
            for (int j = 0; j < 4; ++j) acc1[t][j] = 0.f;

        #pragma unroll
        for (int kt = 0; kt < 8; ++kt) {
            uint32_t a[4];
            uint32_t pan = (kt < 4) ? SM_XS0 : SM_XS1;
            ldmA(a, sbase + pan + sw(rA + (kt & 3) * 32 + colh * 16));
            const uint32_t rB = (uint32_t)((kt * 16 + l15) * 128);
            #pragma unroll
            for (int ntp = 0; ntp < 4; ++ntp) {
                uint32_t b[4];
                ldmBT(b, sbase + w1pan + sw(rB + ntp * 32 + colh * 16));
                mma_f16(acc1[2 * ntp],     a, b);
                mma_f16(acc1[2 * ntp + 1], a, b + 2);
            }
        }

        // prefetch next w1 chunk into the other buffer
        if (ch < 3) {
            const uint4* s1 = (const uint4*)g_w1img[ch + 1];
            uint32_t d = (ch & 1) ? SM_W1A : SM_W1B;
            for (int i = tid; i < 1024; i += 256) cpa16(sbase + d + i * 16, s1 + i);
            CP_COMMIT();
        }

        // ---- epilogue 1: bias + ReLU -> fp16 -> h1 panel ----
        #pragma unroll
        for (int ntp = 0; ntp < 4; ++ntp) {
            #pragma unroll
            for (int h = 0; h < 2; ++h) {
                const int nt = 2 * ntp + h;
                const int n = ntp * 16 + h * 8 + gc * 2;
                const float bb0 = b1s[ch * 64 + n], bb1 = b1s[ch * 64 + n + 1];
                __half2 p0 = __floats2half2_rn(fmaxf(acc1[nt][0] + bb0, 0.f),
                                               fmaxf(acc1[nt][1] + bb1, 0.f));
                __half2 p1 = __floats2half2_rn(fmaxf(acc1[nt][2] + bb0, 0.f),
                                               fmaxf(acc1[nt][3] + bb1, 0.f));
                *(__half2*)(smem + SM_H1 + sw((uint32_t)((r0 + gr) * 128 + n * 2)))     = p0;
                *(__half2*)(smem + SM_H1 + sw((uint32_t)((r0 + 8 + gr) * 128 + n * 2))) = p1;
            }
        }

        if (ch < 3) { CP_WAIT1(); } else { CP_WAIT0(); }   // w2[ch] landed
        __syncthreads();                                   // h1 + w2 visible

        // ---- layer 2 partial: h2 += h1c[16 x 64] @ W2c[64 x 128] ----
        #pragma unroll
        for (int kt = 0; kt < 4; ++kt) {
            uint32_t a[4];
            ldmA(a, sbase + SM_H1 + sw(rA + kt * 32 + colh * 16));
            const uint32_t rB = (uint32_t)((kt * 16 + l15) * 128);
            #pragma unroll
            for (int ntp = 0; ntp < 8; ++ntp) {
                uint32_t b[4];
                uint32_t pan = SM_W2 + (ntp >> 2) * 8192;
                ldmBT(b, sbase + pan + sw(rB + (ntp & 3) * 32 + colh * 16));
                mma_f16(h2acc[2 * ntp],     a, b);
                mma_f16(h2acc[2 * ntp + 1], a, b + 2);
            }
        }
        __syncthreads();   // everyone done reading w2 before refill

        if (ch < 3) {
            const uint4* s2 = (const uint4*)g_w2img[ch + 1];
            for (int i = tid; i < 1024; i += 256) cpa16(sbase + SM_W2 + i * 16, s2 + i);
            CP_COMMIT();
        }
    }

    // ---- epilogue 2: bias2 + ReLU -> fp16, stage, coalesced STG.128 ----
    __half* os = (__half*)(smem + SM_OS);
    #pragma unroll
    for (int ntp = 0; ntp < 8; ++ntp) {
        #pragma unroll
        for (int h = 0; h < 2; ++h) {
            const int nt = 2 * ntp + h;
            const int n = (ntp >> 2) * 64 + (ntp & 3) * 16 + h * 8 + gc * 2;
            const float bb0 = b2s[n], bb1 = b2s[n + 1];
            __half2 p0 = __floats2half2_rn(fmaxf(h2acc[nt][0] + bb0, 0.f),
                                           fmaxf(h2acc[nt][1] + bb1, 0.f));
            __half2 p1 = __floats2half2_rn(fmaxf(h2acc[nt][2] + bb0, 0.f),
                                           fmaxf(h2acc[nt][3] + bb1, 0.f));
            *(__half2*)(os + (r0 + gr) * OS_STRIDE + n)     = p0;
            *(__half2*)(os + (r0 + 8 + gr) * OS_STRIDE + n) = p1;
        }
    }
    __syncthreads();
    {
        uint4* dst = (uint4*)g_h2h + (size_t)blockIdx.x * 2048;
        #pragma unroll 4
        for (int i = tid; i < 2048; i += 256) {
            int r = i >> 4, c8 = (i & 15) * 8;
            dst[i] = *(const uint4*)(os + r * OS_STRIDE + c8);
        }
    }
}

// ============================================================================
// Pool: per-segment mean over fp16 scratch, fp32 accum, deterministic.
// ============================================================================
__global__ void __launch_bounds__(128) pool_kernel(float* __restrict__ out)
{
    const int s = blockIdx.x, c = threadIdx.x;
    const int st = g_segstart[s], en = g_segstart[s + 1];
    const int n = en - st;
    const __half* p = g_h2h + (size_t)st * D_OUT + c;
    float a0 = 0.f, a1 = 0.f, a2 = 0.f, a3 = 0.f;
    int r = 0;
    for (; r + 4 <= n; r += 4) {
        a0 += __half2float(p[0]);
        a1 += __half2float(p[D_OUT]);
        a2 += __half2float(p[2 * D_OUT]);
        a3 += __half2float(p[3 * D_OUT]);
        p += 4 * D_OUT;
    }
    for (; r < n; ++r) { a0 += __half2float(p[0]); p += D_OUT; }
    out[s * D_OUT + c] = ((a0 + a1) + (a2 + a3)) / fmaxf((float)n, 1.f);
}

// ============================================================================
extern "C" void kernel_launch(void* const* d_in, const int* in_sizes, int n_in,
                              void* d_out, int out_size)
{
    const float* x = nullptr; const int* sg = nullptr;
    const float* W1 = nullptr; const float* B1 = nullptr;
    const float* W2 = nullptr; const float* B2 = nullptr;
    int w_seen = 0;
    for (int i = 0; i < n_in; ++i) {
        const int sz = in_sizes[i];
        if (sz == T_TOK * D_IN)      x  = (const float*)d_in[i];
        else if (sz == T_TOK)        sg = (const int*)d_in[i];
        else if (sz == D_IN * D_H) { if (w_seen++ == 0) W1 = (const float*)d_in[i];
                                     else               W2 = (const float*)d_in[i]; }
        else if (sz == D_H)          B1 = (const float*)d_in[i];
        else if (sz == D_OUT)        B2 = (const float*)d_in[i];
    }

    cudaFuncSetAttribute(mlp_kernel, cudaFuncAttributeMaxDynamicSharedMemorySize, SMEM_BYTES);

    prep_weights<<<128, 256>>>(W1, W2);
    prep_bounds<<<(T_TOK + 255) / 256, 256>>>(sg);
    mlp_kernel<<<NTILES, 256, SMEM_BYTES>>>(x, B1, B2);
    pool_kernel<<<N_SEG, 128>>>((float*)d_out);
}

// round 5
// speedup vs baseline: 2.7081x; 1.0148x over previous
#include <cuda_runtime.h>
#include <cuda_fp16.h>
#include <cstdint>

#define T_TOK   262144
#define D_IN    128
#define D_H     256
#define D_OUT   128
#define N_SEG   8192
#define TILE_M  128
#define NTILES  (T_TOK / TILE_M)
#define NCHUNK  4            // D_H chunks of 64

// ---------------- device scratch ----------------
__device__ uint32_t g_w1img[4][4096];   // 4 chunks x 16KB swizzled fp16 [k=128][n=64]
__device__ uint32_t g_w2img[4][4096];   // 4 chunks x 16KB: 2 panels [k=64][n=64]
__device__ int      g_segstart[N_SEG + 1];

// ---------------- SMEM layout (bytes) ----------------
#define SM_B1    0          // fp32[256]
#define SM_B2    1024       // fp32[128]
#define SM_SEG   1536       // int[128] tile segment ids
#define SM_XS0   2048       // x panel k0..63   [128 x 128B] SW128
#define SM_XS1   18432      // x panel k64..127
#define SM_W1A   34816      // w1 buf A [128 x 128B]
#define SM_W1B   51200      // w1 buf B
#define SM_W2    67584      // w2 chunk: 2 panels [64 x 128B] (16KB)
#define SM_H1    83968      // h1 chunk [128 x 128B]
#define SMEM_BYTES 100352   // 98KB -> 2 CTAs/SM
#define SM_OS    2048       // fp32 h2 staging, reuses XS0..W2 (needs 67.6KB < 81.9KB)
#define OS_STRIDE 132       // fp32 row stride

__device__ __forceinline__ uint32_t sw(uint32_t b) { return b ^ ((b >> 3) & 0x70); }

__device__ __forceinline__ uint32_t smem_u32(const void* p) {
    uint32_t a;
    asm("{ .reg .u64 t; cvta.to.shared.u64 t, %1; cvt.u32.u64 %0, t; }" : "=r"(a) : "l"(p));
    return a;
}
__device__ __forceinline__ void ldmA(uint32_t* a, uint32_t addr) {
    asm volatile("ldmatrix.sync.aligned.m8n8.x4.shared.b16 {%0,%1,%2,%3}, [%4];"
        : "=r"(a[0]), "=r"(a[1]), "=r"(a[2]), "=r"(a[3]) : "r"(addr));
}
__device__ __forceinline__ void ldmBT(uint32_t* b, uint32_t addr) {
    asm volatile("ldmatrix.sync.aligned.m8n8.x4.trans.shared.b16 {%0,%1,%2,%3}, [%4];"
        : "=r"(b[0]), "=r"(b[1]), "=r"(b[2]), "=r"(b[3]) : "r"(addr));
}
// fp32-accumulate fp16 MMA (layer 2)
__device__ __forceinline__ void mma_f16(float* c, const uint32_t* a, const uint32_t* b) {
    asm volatile(
        "mma.sync.aligned.m16n8k16.row.col.f32.f16.f16.f32 "
        "{%0,%1,%2,%3}, {%4,%5,%6,%7}, {%8,%9}, {%0,%1,%2,%3};"
        : "+f"(c[0]), "+f"(c[1]), "+f"(c[2]), "+f"(c[3])
        : "r"(a[0]), "r"(a[1]), "r"(a[2]), "r"(a[3]), "r"(b[0]), "r"(b[1]));
}
// fp16-accumulate fp16 MMA (layer 1) — 2x issue rate
__device__ __forceinline__ void mma_f16acc(uint32_t* c, const uint32_t* a, const uint32_t* b) {
    asm volatile(
        "mma.sync.aligned.m16n8k16.row.col.f16.f16.f16.f16 "
        "{%0,%1}, {%2,%3,%4,%5}, {%6,%7}, {%0,%1};"
        : "+r"(c[0]), "+r"(c[1])
        : "r"(a[0]), "r"(a[1]), "r"(a[2]), "r"(a[3]), "r"(b[0]), "r"(b[1]));
}
__device__ __forceinline__ void cpa16(uint32_t saddr, const void* g) {
    asm volatile("cp.async.cg.shared.global [%0], [%1], 16;" :: "r"(saddr), "l"(g));
}
#define CP_COMMIT() asm volatile("cp.async.commit_group;" ::: "memory")
#define CP_WAIT0()  asm volatile("cp.async.wait_group 0;" ::: "memory")
#define CP_WAIT1()  asm volatile("cp.async.wait_group 1;" ::: "memory")

// ============================================================================
// Prep 1: fp16, transposed-for-B, SW128-swizzled weight images
// ============================================================================
__global__ void prep_weights(const float* __restrict__ W1, const float* __restrict__ W2)
{
    int idx = blockIdx.x * blockDim.x + threadIdx.x;     // 0..32767 words
    if (idx < 16384) {                                   // w1
        int ch = idx >> 12, w = idx & 4095;
        uint32_t s = sw(w * 4);
        int k = s >> 7, nl = (s & 127) >> 1;
        __half2 v = __floats2half2_rn(W1[k * D_H + ch * 64 + nl],
                                      W1[k * D_H + ch * 64 + nl + 1]);
        g_w1img[ch][w] = *(uint32_t*)&v;
    } else {                                             // w2
        int i2 = idx - 16384;
        int ch = i2 >> 12, w = i2 & 4095;
        int p = w >> 11, wi = w & 2047;
        uint32_t s = sw(wi * 4);
        int kl = s >> 7, nl = (s & 127) >> 1;
        int k = ch * 64 + kl, n = p * 64 + nl;
        __half2 v = __floats2half2_rn(W2[k * D_OUT + n], W2[k * D_OUT + n + 1]);
        g_w2img[ch][w] = *(uint32_t*)&v;
    }
}

// Prep 2: segment start offsets (ids sorted)
__global__ void prep_bounds(const int* __restrict__ seg)
{
    int i = blockIdx.x * blockDim.x + threadIdx.x;
    if (i >= T_TOK) return;
    int s  = seg[i];
    int sp = (i == 0) ? -1 : seg[i - 1];
    for (int t = sp + 1; t <= s; ++t) g_segstart[t] = i;
    if (i == T_TOK - 1)
        for (int t = s + 1; t <= N_SEG; ++t) g_segstart[t] = T_TOK;
}

// Zero the output accumulator (d_out is poisoned before timing)
__global__ void zero_out(float* __restrict__ out)
{
    out[blockIdx.x * 512 + threadIdx.x] = 0.f;
}

// Final: divide pooled sums by counts
__global__ void divide_kernel(float* __restrict__ out)
{
    const int s = blockIdx.x;
    const int n = g_segstart[s + 1] - g_segstart[s];
    out[s * D_OUT + threadIdx.x] *= (1.f / (float)max(n, 1));
}

// ============================================================================
// Fused MLP + segment-sum. CTA = 128 tokens, 8 warps x 16 rows, occ 2.
// ============================================================================
__global__ void __launch_bounds__(256, 2) mlp_kernel(
    const float* __restrict__ x, const int* __restrict__ seg,
    const float* __restrict__ b1, const float* __restrict__ b2,
    float* __restrict__ out)
{
    extern __shared__ char smem[];
    const uint32_t sbase = smem_u32(smem);
    const int tid = threadIdx.x, wid = tid >> 5, lane = tid & 31;
    const int l15 = lane & 15;
    const int colh = (lane >> 4) & 1;
    const int gr = lane >> 2, gc = lane & 3;
    const int r0 = wid * 16;
    const long tile0 = (long)blockIdx.x * TILE_M;

    float* b1s = (float*)(smem + SM_B1);
    float* b2s = (float*)(smem + SM_B2);
    int*   segs = (int*)(smem + SM_SEG);
    b1s[tid] = b1[tid & 255];
    if (tid < D_OUT) b2s[tid] = b2[tid];
    if (tid < TILE_M) segs[tid] = seg[tile0 + tid];

    // ---- stage x -> fp16 SW128 panels ----
    {
        const float4* xg = (const float4*)(x + tile0 * D_IN);
        #pragma unroll 4
        for (int i = tid; i < TILE_M * D_IN / 4; i += 256) {
            float4 v = xg[i];
            int r = i >> 5, k0 = (i & 31) * 4;
            uint32_t pan = (k0 >= 64) ? SM_XS1 : SM_XS0;
            uint32_t a = sbase + pan + sw((uint32_t)(r * 128 + (k0 & 63) * 2));
            __half2 h0 = __floats2half2_rn(v.x, v.y);
            __half2 h1 = __floats2half2_rn(v.z, v.w);
            asm volatile("st.shared.v2.b32 [%0], {%1,%2};"
                :: "r"(a), "r"(*(uint32_t*)&h0), "r"(*(uint32_t*)&h1) : "memory");
        }
    }
    // ---- prefetch w1[0], w2[0] ----
    {
        const uint4* s1 = (const uint4*)g_w1img[0];
        for (int i = tid; i < 1024; i += 256) cpa16(sbase + SM_W1A + i * 16, s1 + i);
        CP_COMMIT();
        const uint4* s2 = (const uint4*)g_w2img[0];
        for (int i = tid; i < 1024; i += 256) cpa16(sbase + SM_W2 + i * 16, s2 + i);
        CP_COMMIT();
    }

    const uint32_t rA = (uint32_t)((r0 + l15) * 128);

    float h2acc[16][4];
    #pragma unroll
    for (int t = 0; t < 16; ++t)
        #pragma unroll
        for (int j = 0; j < 4; ++j) h2acc[t][j] = 0.f;

    #pragma unroll 1
    for (int ch = 0; ch < NCHUNK; ++ch) {
        CP_WAIT1();
        __syncthreads();

        const uint32_t w1pan = (ch & 1) ? SM_W1B : SM_W1A;

        // ---- layer 1 (fp16 acc): acc1[16 x 64] = x[16 x 128] @ W1c[128 x 64] ----
        uint32_t acc1[8][2];
        #pragma unroll
        for (int t = 0; t < 8; ++t) { acc1[t][0] = 0u; acc1[t][1] = 0u; }

        #pragma unroll
        for (int kt = 0; kt < 8; ++kt) {
            uint32_t a[4];
            uint32_t pan = (kt < 4) ? SM_XS0 : SM_XS1;
            ldmA(a, sbase + pan + sw(rA + (kt & 3) * 32 + colh * 16));
            const uint32_t rB = (uint32_t)((kt * 16 + l15) * 128);
            #pragma unroll
            for (int ntp = 0; ntp < 4; ++ntp) {
                uint32_t b[4];
                ldmBT(b, sbase + w1pan + sw(rB + ntp * 32 + colh * 16));
                mma_f16acc(acc1[2 * ntp],     a, b);
                mma_f16acc(acc1[2 * ntp + 1], a, b + 2);
            }
        }

        if (ch < 3) {
            const uint4* s1 = (const uint4*)g_w1img[ch + 1];
            uint32_t d = (ch & 1) ? SM_W1A : SM_W1B;
            for (int i = tid; i < 1024; i += 256) cpa16(sbase + d + i * 16, s1 + i);
            CP_COMMIT();
        }

        // ---- epilogue 1: fp16 bias + ReLU -> h1 panel ----
        const __half2 z2 = __float2half2_rn(0.f);
        #pragma unroll
        for (int ntp = 0; ntp < 4; ++ntp) {
            #pragma unroll
            for (int h = 0; h < 2; ++h) {
                const int nt = 2 * ntp + h;
                const int n = ntp * 16 + h * 8 + gc * 2;
                const __half2 bb = __floats2half2_rn(b1s[ch * 64 + n], b1s[ch * 64 + n + 1]);
                __half2 p0 = __hmax2(__hadd2(*(__half2*)&acc1[nt][0], bb), z2);
                __half2 p1 = __hmax2(__hadd2(*(__half2*)&acc1[nt][1], bb), z2);
                *(__half2*)(smem + SM_H1 + sw((uint32_t)((r0 + gr) * 128 + n * 2)))     = p0;
                *(__half2*)(smem + SM_H1 + sw((uint32_t)((r0 + 8 + gr) * 128 + n * 2))) = p1;
            }
        }

        if (ch < 3) { CP_WAIT1(); } else { CP_WAIT0(); }
        __syncthreads();

        // ---- layer 2 (fp32 acc): h2 += h1c[16 x 64] @ W2c[64 x 128] ----
        #pragma unroll
        for (int kt = 0; kt < 4; ++kt) {
            uint32_t a[4];
            ldmA(a, sbase + SM_H1 + sw(rA + kt * 32 + colh * 16));
            const uint32_t rB = (uint32_t)((kt * 16 + l15) * 128);
            #pragma unroll
            for (int ntp = 0; ntp < 8; ++ntp) {
                uint32_t b[4];
                uint32_t pan = SM_W2 + (ntp >> 2) * 8192;
                ldmBT(b, sbase + pan + sw(rB + (ntp & 3) * 32 + colh * 16));
                mma_f16(h2acc[2 * ntp],     a, b);
                mma_f16(h2acc[2 * ntp + 1], a, b + 2);
            }
        }
        __syncthreads();

        if (ch < 3) {
            const uint4* s2 = (const uint4*)g_w2img[ch + 1];
            for (int i = tid; i < 1024; i += 256) cpa16(sbase + SM_W2 + i * 16, s2 + i);
            CP_COMMIT();
        }
    }

    // ---- epilogue 2: bias2 + ReLU -> fp32 staging ----
    float* os = (float*)(smem + SM_OS);
    #pragma unroll
    for (int ntp = 0; ntp < 8; ++ntp) {
        #pragma unroll
        for (int h = 0; h < 2; ++h) {
            const int nt = 2 * ntp + h;
            const int n = (ntp >> 2) * 64 + (ntp & 3) * 16 + h * 8 + gc * 2;
            const float bb0 = b2s[n], bb1 = b2s[n + 1];
            os[(r0 + gr) * OS_STRIDE + n]         = fmaxf(h2acc[nt][0] + bb0, 0.f);
            os[(r0 + gr) * OS_STRIDE + n + 1]     = fmaxf(h2acc[nt][1] + bb1, 0.f);
            os[(r0 + 8 + gr) * OS_STRIDE + n]     = fmaxf(h2acc[nt][2] + bb0, 0.f);
            os[(r0 + 8 + gr) * OS_STRIDE + n + 1] = fmaxf(h2acc[nt][3] + bb1, 0.f);
        }
    }
    __syncthreads();

    // ---- fused segment-sum: column-parallel run scan + one atomic per run ----
    {
        const int c  = tid & 127;
        const int rs = (tid >> 7) * 64;        // rows rs .. rs+63
        float acc = 0.f;
        int cur = segs[rs];
        #pragma unroll 4
        for (int r = rs; r < rs + 64; ++r) {
            acc += os[r * OS_STRIDE + c];
            const int nxt = (r + 1 < TILE_M) ? segs[r + 1] : -1;
            if (r == rs + 63 || nxt != cur) {
                atomicAdd(&out[cur * D_OUT + c], acc);
                acc = 0.f;
                cur = nxt;
            }
        }
    }
}

// ============================================================================
extern "C" void kernel_launch(void* const* d_in, const int* in_sizes, int n_in,
                              void* d_out, int out_size)
{
    const float* x = nullptr; const int* sg = nullptr;
    const float* W1 = nullptr; const float* B1 = nullptr;
    const float* W2 = nullptr; const float* B2 = nullptr;
    int w_seen = 0;
    for (int i = 0; i < n_in; ++i) {
        const int sz = in_sizes[i];
        if (sz == T_TOK * D_IN)      x  = (const float*)d_in[i];
        else if (sz == T_TOK)        sg = (const int*)d_in[i];
        else if (sz == D_IN * D_H) { if (w_seen++ == 0) W1 = (const float*)d_in[i];
                                     else               W2 = (const float*)d_in[i]; }
        else if (sz == D_H)          B1 = (const float*)d_in[i];
        else if (sz == D_OUT)        B2 = (const float*)d_in[i];
    }

    cudaFuncSetAttribute(mlp_kernel, cudaFuncAttributeMaxDynamicSharedMemorySize, SMEM_BYTES);

    prep_weights<<<128, 256>>>(W1, W2);
    prep_bounds<<<(T_TOK + 255) / 256, 256>>>(sg);
    zero_out<<<(N_SEG * D_OUT) / 512, 512>>>((float*)d_out);
    mlp_kernel<<<NTILES, 256, SMEM_BYTES>>>(x, sg, B1, B2, (float*)d_out);
    divide_kernel<<<N_SEG, 128>>>((float*)d_out);
}

// round 6
// speedup vs baseline: 3.0577x; 1.1291x over previous
#include <cuda_runtime.h>
#include <cuda_fp16.h>
#include <cstdint>

#define T_TOK   262144
#define D_IN    128
#define D_H     256
#define D_OUT   128
#define N_SEG   8192
#define TILE_M  128
#define NTILES  (T_TOK / TILE_M)
#define NCHUNK  4            // D_H chunks of 64

// ---------------- device scratch ----------------
__device__ uint32_t g_w1img[4][4096];   // 4 chunks x 16KB swizzled fp16 [k=128][n=64]
__device__ uint32_t g_w2img[4][4096];   // 4 chunks x 16KB: 2 panels [k=64][n=64]
__device__ int      g_segstart[N_SEG + 1];

// ---------------- SMEM layout (bytes) ----------------
#define SM_B1    0          // fp32[256]
#define SM_B2    1024       // fp32[128]
#define SM_SEG   1536       // int[128] tile segment ids
#define SM_XS0   2048       // x panel k0..63   [128 x 128B] SW128
#define SM_XS1   18432      // x panel k64..127
#define SM_W1A   34816      // w1 buf A [128 x 128B]
#define SM_W1B   51200      // w1 buf B
#define SM_W2    67584      // w2 chunk: 2 panels [64 x 128B] (16KB)
#define SM_H1    83968      // h1 chunk [128 x 128B]
#define SMEM_BYTES 100352   // 98KB -> 2 CTAs/SM
#define SM_OS    2048       // fp16 h2 staging (34.8KB), reuses XS0/XS1/W1A-head
#define OS_STRIDE 136       // half stride (272B rows)

__device__ __forceinline__ uint32_t sw(uint32_t b) { return b ^ ((b >> 3) & 0x70); }

__device__ __forceinline__ uint32_t smem_u32(const void* p) {
    uint32_t a;
    asm("{ .reg .u64 t; cvta.to.shared.u64 t, %1; cvt.u32.u64 %0, t; }" : "=r"(a) : "l"(p));
    return a;
}
__device__ __forceinline__ void ldmA(uint32_t* a, uint32_t addr) {
    asm volatile("ldmatrix.sync.aligned.m8n8.x4.shared.b16 {%0,%1,%2,%3}, [%4];"
        : "=r"(a[0]), "=r"(a[1]), "=r"(a[2]), "=r"(a[3]) : "r"(addr));
}
__device__ __forceinline__ void ldmBT(uint32_t* b, uint32_t addr) {
    asm volatile("ldmatrix.sync.aligned.m8n8.x4.trans.shared.b16 {%0,%1,%2,%3}, [%4];"
        : "=r"(b[0]), "=r"(b[1]), "=r"(b[2]), "=r"(b[3]) : "r"(addr));
}
// fp32-accumulate fp16 MMA (layer 2)
__device__ __forceinline__ void mma_f16(float* c, const uint32_t* a, const uint32_t* b) {
    asm volatile(
        "mma.sync.aligned.m16n8k16.row.col.f32.f16.f16.f32 "
        "{%0,%1,%2,%3}, {%4,%5,%6,%7}, {%8,%9}, {%0,%1,%2,%3};"
        : "+f"(c[0]), "+f"(c[1]), "+f"(c[2]), "+f"(c[3])
        : "r"(a[0]), "r"(a[1]), "r"(a[2]), "r"(a[3]), "r"(b[0]), "r"(b[1]));
}
// fp16-accumulate fp16 MMA (layer 1)
__device__ __forceinline__ void mma_f16acc(uint32_t* c, const uint32_t* a, const uint32_t* b) {
    asm volatile(
        "mma.sync.aligned.m16n8k16.row.col.f16.f16.f16.f16 "
        "{%0,%1}, {%2,%3,%4,%5}, {%6,%7}, {%0,%1};"
        : "+r"(c[0]), "+r"(c[1])
        : "r"(a[0]), "r"(a[1]), "r"(a[2]), "r"(a[3]), "r"(b[0]), "r"(b[1]));
}
__device__ __forceinline__ void cpa16(uint32_t saddr, const void* g) {
    asm volatile("cp.async.cg.shared.global [%0], [%1], 16;" :: "r"(saddr), "l"(g));
}
#define CP_COMMIT() asm volatile("cp.async.commit_group;" ::: "memory")
#define CP_WAIT0()  asm volatile("cp.async.wait_group 0;" ::: "memory")
#define CP_WAIT1()  asm volatile("cp.async.wait_group 1;" ::: "memory")

// ============================================================================
// Prep 1: fp16, transposed-for-B, SW128-swizzled weight images
// ============================================================================
__global__ void prep_weights(const float* __restrict__ W1, const float* __restrict__ W2)
{
    int idx = blockIdx.x * blockDim.x + threadIdx.x;     // 0..32767 words
    if (idx < 16384) {                                   // w1
        int ch = idx >> 12, w = idx & 4095;
        uint32_t s = sw(w * 4);
        int k = s >> 7, nl = (s & 127) >> 1;
        __half2 v = __floats2half2_rn(W1[k * D_H + ch * 64 + nl],
                                      W1[k * D_H + ch * 64 + nl + 1]);
        g_w1img[ch][w] = *(uint32_t*)&v;
    } else {                                             // w2
        int i2 = idx - 16384;
        int ch = i2 >> 12, w = i2 & 4095;
        int p = w >> 11, wi = w & 2047;
        uint32_t s = sw(wi * 4);
        int kl = s >> 7, nl = (s & 127) >> 1;
        int k = ch * 64 + kl, n = p * 64 + nl;
        __half2 v = __floats2half2_rn(W2[k * D_OUT + n], W2[k * D_OUT + n + 1]);
        g_w2img[ch][w] = *(uint32_t*)&v;
    }
}

// Prep 2: segment start offsets (ids sorted)
__global__ void prep_bounds(const int* __restrict__ seg)
{
    int i = blockIdx.x * blockDim.x + threadIdx.x;
    if (i >= T_TOK) return;
    int s  = seg[i];
    int sp = (i == 0) ? -1 : seg[i - 1];
    for (int t = sp + 1; t <= s; ++t) g_segstart[t] = i;
    if (i == T_TOK - 1)
        for (int t = s + 1; t <= N_SEG; ++t) g_segstart[t] = T_TOK;
}

// Zero the output accumulator (d_out is poisoned before timing)
__global__ void zero_out(float* __restrict__ out)
{
    out[blockIdx.x * 512 + threadIdx.x] = 0.f;
}

// Final: divide pooled sums by counts
__global__ void divide_kernel(float* __restrict__ out)
{
    const int s = blockIdx.x;
    const int n = g_segstart[s + 1] - g_segstart[s];
    out[s * D_OUT + threadIdx.x] *= (1.f / (float)max(n, 1));
}

// ============================================================================
// Fused MLP + segment-sum. CTA = 128 tokens, warp grid = 4 m-groups x 2 n-splits.
// Each warp: 32 token rows, half the N columns. B smem traffic halved vs R5.
// ============================================================================
__global__ void __launch_bounds__(256, 2) mlp_kernel(
    const float* __restrict__ x, const int* __restrict__ seg,
    const float* __restrict__ b1, const float* __restrict__ b2,
    float* __restrict__ out)
{
    extern __shared__ char smem[];
    const uint32_t sbase = smem_u32(smem);
    const int tid = threadIdx.x, wid = tid >> 5, lane = tid & 31;
    const int l15 = lane & 15;
    const int colh = (lane >> 4) & 1;
    const int gr = lane >> 2, gc = lane & 3;
    const int mg = wid & 3;            // m-group: rows mg*32 .. +31
    const int ns = wid >> 2;           // n-split half
    const long tile0 = (long)blockIdx.x * TILE_M;

    float* b1s = (float*)(smem + SM_B1);
    float* b2s = (float*)(smem + SM_B2);
    int*   segs = (int*)(smem + SM_SEG);
    b1s[tid] = b1[tid & 255];
    if (tid < D_OUT) b2s[tid] = b2[tid];
    if (tid < TILE_M) segs[tid] = seg[tile0 + tid];

    // ---- stage x -> fp16 SW128 panels ----
    {
        const float4* xg = (const float4*)(x + tile0 * D_IN);
        #pragma unroll 4
        for (int i = tid; i < TILE_M * D_IN / 4; i += 256) {
            float4 v = xg[i];
            int r = i >> 5, k0 = (i & 31) * 4;
            uint32_t pan = (k0 >= 64) ? SM_XS1 : SM_XS0;
            uint32_t a = sbase + pan + sw((uint32_t)(r * 128 + (k0 & 63) * 2));
            __half2 h0 = __floats2half2_rn(v.x, v.y);
            __half2 h1 = __floats2half2_rn(v.z, v.w);
            asm volatile("st.shared.v2.b32 [%0], {%1,%2};"
                :: "r"(a), "r"(*(uint32_t*)&h0), "r"(*(uint32_t*)&h1) : "memory");
        }
    }
    // ---- prefetch w1[0], w2[0] ----
    {
        const uint4* s1 = (const uint4*)g_w1img[0];
        for (int i = tid; i < 1024; i += 256) cpa16(sbase + SM_W1A + i * 16, s1 + i);
        CP_COMMIT();
        const uint4* s2 = (const uint4*)g_w2img[0];
        for (int i = tid; i < 1024; i += 256) cpa16(sbase + SM_W2 + i * 16, s2 + i);
        CP_COMMIT();
    }

    const uint32_t rA0 = (uint32_t)((mg * 32 + l15) * 128);        // mt0 A rows
    const uint32_t rA1 = (uint32_t)((mg * 32 + 16 + l15) * 128);   // mt1 A rows

    float h2acc[2][8][4];   // [mt][n8][frag]
    #pragma unroll
    for (int mt = 0; mt < 2; ++mt)
        #pragma unroll
        for (int t = 0; t < 8; ++t)
            #pragma unroll
            for (int j = 0; j < 4; ++j) h2acc[mt][t][j] = 0.f;

    #pragma unroll 1
    for (int ch = 0; ch < NCHUNK; ++ch) {
        CP_WAIT1();
        __syncthreads();

        const uint32_t w1pan = (ch & 1) ? SM_W1B : SM_W1A;

        // ---- layer 1 (fp16 acc): rows [mg*32,+32) x chunk cols [ns*32,+32) ----
        uint32_t acc1[2][4][2];
        #pragma unroll
        for (int mt = 0; mt < 2; ++mt)
            #pragma unroll
            for (int t = 0; t < 4; ++t) { acc1[mt][t][0] = 0u; acc1[mt][t][1] = 0u; }

        #pragma unroll
        for (int kt = 0; kt < 8; ++kt) {
            const uint32_t pan = (kt < 4) ? SM_XS0 : SM_XS1;
            const uint32_t kb = (kt & 3) * 32 + colh * 16;
            uint32_t a0[4], a1[4];
            ldmA(a0, sbase + pan + sw(rA0 + kb));
            ldmA(a1, sbase + pan + sw(rA1 + kb));
            const uint32_t rB = (uint32_t)((kt * 16 + l15) * 128);
            #pragma unroll
            for (int ntp = 0; ntp < 2; ++ntp) {
                uint32_t b[4];
                ldmBT(b, sbase + w1pan + sw(rB + ns * 64 + ntp * 32 + colh * 16));
                mma_f16acc(acc1[0][ntp * 2],     a0, b);
                mma_f16acc(acc1[0][ntp * 2 + 1], a0, b + 2);
                mma_f16acc(acc1[1][ntp * 2],     a1, b);
                mma_f16acc(acc1[1][ntp * 2 + 1], a1, b + 2);
            }
        }

        if (ch < 3) {
            const uint4* s1 = (const uint4*)g_w1img[ch + 1];
            uint32_t d = (ch & 1) ? SM_W1A : SM_W1B;
            for (int i = tid; i < 1024; i += 256) cpa16(sbase + d + i * 16, s1 + i);
            CP_COMMIT();
        }

        // ---- epilogue 1: fp16 bias + ReLU -> h1 slab [32 rows x 32 cols] ----
        const __half2 z2 = __float2half2_rn(0.f);
        #pragma unroll
        for (int mt = 0; mt < 2; ++mt) {
            #pragma unroll
            for (int ntp = 0; ntp < 2; ++ntp) {
                #pragma unroll
                for (int h = 0; h < 2; ++h) {
                    const int n = ns * 32 + ntp * 16 + h * 8 + gc * 2;   // chunk-local col
                    const __half2 bb = __floats2half2_rn(b1s[ch * 64 + n], b1s[ch * 64 + n + 1]);
                    const int row0 = mg * 32 + mt * 16 + gr;
                    __half2 p0 = __hmax2(__hadd2(*(__half2*)&acc1[mt][ntp * 2 + h][0], bb), z2);
                    __half2 p1 = __hmax2(__hadd2(*(__half2*)&acc1[mt][ntp * 2 + h][1], bb), z2);
                    *(__half2*)(smem + SM_H1 + sw((uint32_t)(row0 * 128 + n * 2)))       = p0;
                    *(__half2*)(smem + SM_H1 + sw((uint32_t)((row0 + 8) * 128 + n * 2))) = p1;
                }
            }
        }

        if (ch < 3) { CP_WAIT1(); } else { CP_WAIT0(); }
        __syncthreads();

        // ---- layer 2 (fp32 acc): rows [mg*32,+32) x out cols [ns*64,+64) ----
        const uint32_t w2pan = SM_W2 + (uint32_t)ns * 8192;
        #pragma unroll
        for (int kt = 0; kt < 4; ++kt) {
            const uint32_t kb = kt * 32 + colh * 16;
            uint32_t a0[4], a1[4];
            ldmA(a0, sbase + SM_H1 + sw(rA0 + kb));
            ldmA(a1, sbase + SM_H1 + sw(rA1 + kb));
            const uint32_t rB = (uint32_t)((kt * 16 + l15) * 128);
            #pragma unroll
            for (int ntp = 0; ntp < 4; ++ntp) {
                uint32_t b[4];
                ldmBT(b, sbase + w2pan + sw(rB + ntp * 32 + colh * 16));
                mma_f16(h2acc[0][ntp * 2],     a0, b);
                mma_f16(h2acc[0][ntp * 2 + 1], a0, b + 2);
                mma_f16(h2acc[1][ntp * 2],     a1, b);
                mma_f16(h2acc[1][ntp * 2 + 1], a1, b + 2);
            }
        }
        __syncthreads();

        if (ch < 3) {
            const uint4* s2 = (const uint4*)g_w2img[ch + 1];
            for (int i = tid; i < 1024; i += 256) cpa16(sbase + SM_W2 + i * 16, s2 + i);
            CP_COMMIT();
        }
    }

    // ---- epilogue 2: bias2 + ReLU -> fp16 staging ----
    __half* os = (__half*)(smem + SM_OS);
    #pragma unroll
    for (int mt = 0; mt < 2; ++mt) {
        #pragma unroll
        for (int ntp = 0; ntp < 4; ++ntp) {
            #pragma unroll
            for (int h = 0; h < 2; ++h) {
                const int j = ntp * 2 + h;
                const int n = ns * 64 + ntp * 16 + h * 8 + gc * 2;
                const float bb0 = b2s[n], bb1 = b2s[n + 1];
                const int row0 = mg * 32 + mt * 16 + gr;
                __half2 p0 = __floats2half2_rn(fmaxf(h2acc[mt][j][0] + bb0, 0.f),
                                               fmaxf(h2acc[mt][j][1] + bb1, 0.f));
                __half2 p1 = __floats2half2_rn(fmaxf(h2acc[mt][j][2] + bb0, 0.f),
                                               fmaxf(h2acc[mt][j][3] + bb1, 0.f));
                *(__half2*)(os + row0 * OS_STRIDE + n)       = p0;
                *(__half2*)(os + (row0 + 8) * OS_STRIDE + n) = p1;
            }
        }
    }
    __syncthreads();

    // ---- fused segment-sum: column-parallel run scan + one atomic per run ----
    {
        const int c  = tid & 127;
        const int rs = (tid >> 7) * 64;        // rows rs .. rs+63
        float acc = 0.f;
        int cur = segs[rs];
        #pragma unroll 4
        for (int r = rs; r < rs + 64; ++r) {
            acc += __half2float(os[r * OS_STRIDE + c]);
            const int nxt = (r + 1 < TILE_M) ? segs[r + 1] : -1;
            if (r == rs + 63 || nxt != cur) {
                atomicAdd(&out[cur * D_OUT + c], acc);
                acc = 0.f;
                cur = nxt;
            }
        }
    }
}

// ============================================================================
extern "C" void kernel_launch(void* const* d_in, const int* in_sizes, int n_in,
                              void* d_out, int out_size)
{
    const float* x = nullptr; const int* sg = nullptr;
    const float* W1 = nullptr; const float* B1 = nullptr;
    const float* W2 = nullptr; const float* B2 = nullptr;
    int w_seen = 0;
    for (int i = 0; i < n_in; ++i) {
        const int sz = in_sizes[i];
        if (sz == T_TOK * D_IN)      x  = (const float*)d_in[i];
        else if (sz == T_TOK)        sg = (const int*)d_in[i];
        else if (sz == D_IN * D_H) { if (w_seen++ == 0) W1 = (const float*)d_in[i];
                                     else               W2 = (const float*)d_in[i]; }
        else if (sz == D_H)          B1 = (const float*)d_in[i];
        else if (sz == D_OUT)        B2 = (const float*)d_in[i];
    }

    cudaFuncSetAttribute(mlp_kernel, cudaFuncAttributeMaxDynamicSharedMemorySize, SMEM_BYTES);

    prep_weights<<<128, 256>>>(W1, W2);
    prep_bounds<<<(T_TOK + 255) / 256, 256>>>(sg);
    zero_out<<<(N_SEG * D_OUT) / 512, 512>>>((float*)d_out);
    mlp_kernel<<<NTILES, 256, SMEM_BYTES>>>(x, sg, B1, B2, (float*)d_out);
    divide_kernel<<<N_SEG, 128>>>((float*)d_out);
}